// round 6
// baseline (speedup 1.0000x reference)
#include <cuda_runtime.h>
#include <math.h>

#define NMODES   6400
#define MDIM     80
#define NCHUNK   128
#define CHUNK    (NMODES / NCHUNK)      /* 50 modes per chunk = 25 pairs */
#define MAX_T    24576
#define TW       32                      /* samples per thread, stride 32 */
#define SPAN     1024                    /* samples per warp tile */
#define WPB      4                       /* warps per block in k1 */

#define KF   ((float)(1.0 / 44100.0))
#define K2F  ((float)((1.0/44100.0)*(1.0/44100.0)))

// per-mode tables
__device__ float4   g_P0[NMODES];   // {theta, sigma, C, a}
__device__ float4   g_P1[NMODES];   // {b, z1c, z1s, Z16c}
__device__ float    g_P2[NMODES];   // {Z16s}
__device__ float    g_part[NCHUNK][MAX_T];
__device__ unsigned g_maxbits;
__device__ unsigned g_bar;

// ---------------------------------------------------------------------------
// Accurate flag-proof sine / sincos. Cody-Waite 3-term reduction (exact for
// |n| < 2^15), minimax polys.
// ---------------------------------------------------------------------------
__device__ __forceinline__ float sin_acc(float x) {
    const float INV_PI = 0.318309886183790671538f;
    float nf = rintf(__fmul_rn(x, INV_PI));
    int   ni = (int)nf;
    float r = __fmaf_rn(-nf, 3.140625f, x);
    r = __fmaf_rn(-nf, 9.670257568359375e-4f, r);
    r = __fmaf_rn(-nf, 6.2771141529083252e-7f, r);
    float r2 = __fmul_rn(r, r);
    float p  = __fmaf_rn(2.60831598097865935e-06f, r2, -1.98106907191686332e-4f);
    p = __fmaf_rn(p, r2,  8.33307858556509018e-3f);
    p = __fmaf_rn(p, r2, -0.166666597127914429f);
    float s = __fmaf_rn(__fmul_rn(r, r2), p, r);
    return __int_as_float(__float_as_int(s) ^ ((ni & 1) << 31));
}

__device__ __forceinline__ void sincos_acc(float x, float& so, float& co) {
    const float INV_PI = 0.318309886183790671538f;
    float nf = rintf(__fmul_rn(x, INV_PI));
    int   sgn = ((int)nf & 1) << 31;
    float r = __fmaf_rn(-nf, 3.140625f, x);
    r = __fmaf_rn(-nf, 9.670257568359375e-4f, r);
    r = __fmaf_rn(-nf, 6.2771141529083252e-7f, r);
    float r2 = __fmul_rn(r, r);
    float ps = __fmaf_rn(2.60831598097865935e-06f, r2, -1.98106907191686332e-4f);
    ps = __fmaf_rn(ps, r2,  8.33307858556509018e-3f);
    ps = __fmaf_rn(ps, r2, -0.166666597127914429f);
    float s = __fmaf_rn(__fmul_rn(r, r2), ps, r);
    float pc = __fmaf_rn(2.44331571e-5f, r2, -1.38873162e-3f);
    pc = __fmaf_rn(pc, r2, 4.16666456e-2f);
    pc = __fmaf_rn(pc, r2, -0.5f);
    float c = __fmaf_rn(pc, r2, 1.0f);
    so = __int_as_float(__float_as_int(s) ^ sgn);
    co = __int_as_float(__float_as_int(c) ^ sgn);
}

__device__ __forceinline__ double softplus_d(double x) {
    return (x > 0.0) ? x + log1p(exp(-x)) : log1p(exp(x));
}
__device__ __forceinline__ float sigmoid_of(float argf) {
    return (float)(1.0 / (1.0 + exp(-(double)argf)));
}

// ---------------------------------------------------------------------------
// k0: per-mode setup (32-thread blocks -> spread over SMs). Phase-critical
// chain in explicit f32 RN; recurrence/rotation/resync coeffs in double.
// ---------------------------------------------------------------------------
__global__ void k0_setup(const float* __restrict__ mu_raw,
                         const float* __restrict__ D_raw,
                         const float* __restrict__ T0_raw,
                         const float* __restrict__ Ly_raw,
                         const float* __restrict__ xo_raw,
                         const float* __restrict__ yo_raw) {
    int m = blockIdx.x * blockDim.x + threadIdx.x;
    if (m == 0) { g_maxbits = 0u; g_bar = 0u; }
    if (m >= NMODES) return;

    float mu  = __fadd_rn((float)softplus_d((double)*mu_raw),  1e-4f);
    float Dm  = __fadd_rn((float)softplus_d((double)*D_raw),   1e-4f);
    float T0m = __fadd_rn((float)softplus_d((double)*T0_raw),  1e-4f);

    float hLy = __fmul_rn(__fadd_rn((float)tanh((double)*Ly_raw), 1.0f), 0.5f);
    float Ly  = __fadd_rn(1.1f, __fmul_rn(2.9f, hLy));
    float hx  = __fmul_rn(__fadd_rn((float)tanh((double)*xo_raw), 1.0f), 0.5f);
    float xo  = __fadd_rn(0.49f, __fmul_rn(0.51f, hx));
    float hy  = __fmul_rn(__fadd_rn((float)tanh((double)*yo_raw), 1.0f), 0.5f);
    float yo  = __fadd_rn(__fmul_rn(0.51f, Ly), __fmul_rn(__fmul_rn(0.49f, Ly), hy));
    float yi  = __fmul_rn(0.467f, Ly);

    int mi = m / MDIM + 1;
    int nj = m % MDIM + 1;
    const float PIf = (float)M_PI;

    // phase-critical: g1 -> omega -> theta, explicit f32 RN chain
    float mf = (float)mi, nf = (float)nj;
    float t1 = __fmul_rn(mf, PIf);
    float t2 = __fdiv_rn(__fmul_rn(nf, PIf), Ly);
    float g1 = __fadd_rn(__fmul_rn(t1, t1), __fmul_rn(t2, t2));
    float om_sq = __fadd_rn(__fmul_rn(T0m, g1),
                            __fmul_rn(__fmul_rn(Dm, g1), g1));
    float omega = __fsqrt_rn(fmaxf(om_sq, 0.0f));
    float theta = __fmul_rn(omega, KF);

    const double OM2d   = 2.0 * M_PI * 500.0;
    const double DOMSQd = OM2d * OM2d;
    const double ALPHAd = 3.0 * log(10.0) / DOMSQd * (DOMSQd / 6.0);
    const double BETAd  = 3.0 * log(10.0) / DOMSQd * (1.0 / 2.0 - 1.0 / 6.0);
    float om2f  = __fmul_rn(omega, omega);
    float sigma = __fadd_rn((float)ALPHAd, __fmul_rn((float)BETAd, om2f));

    const float MAXOMf = (float)(10000.0 * 2.0 * M_PI);
    const float LOWOMf = (float)(20.0 * 2.0 * M_PI);
    float a1 = __fdiv_rn(__fsub_rn(MAXOMf, omega), 100.0f);
    float a2 = __fdiv_rn(__fsub_rn(omega, LOWOMf), 100.0f);
    float valid = __fmul_rn(sigmoid_of(a1), sigmoid_of(a2));

    double PId = (double)PIf;
    float inw = __fmul_rn((float)cos(0.335 * PId * (double)mi),
                          (float)cos((double)yi * PId * (double)nj / (double)Ly));
    float outw = __fmul_rn((float)cos((double)xo * PId * (double)mi),
                           (float)cos((double)yo * PId * (double)nj / (double)Ly));

    float ms = __fmul_rn(__fmul_rn(0.25f, mu), Ly);
    float E  = (float)exp(-(double)__fmul_rn(sigma, KF));
    float P  = __fmul_rn(outw, inw);
    P = __fmul_rn(P, K2F);
    P = __fmul_rn(P, E);
    P = __fdiv_rn(P, ms);
    P = __fmul_rn(P, valid);

    float coef = __fdiv_rn(P, __fadd_rn(sin_acc(theta), 1e-8f));

    // stride-32 recurrence + rotation + resync coefficients (double)
    double sd   = (double)sigma;
    double Kd   = 1.0 / 44100.0;
    double r32d = exp(-32.0 * sd * Kd);
    double Th32 = 32.0 * (double)theta;
    double c32d = cos(Th32), s32d = sin(Th32);
    float  a    = (float)(2.0 * r32d * c32d);
    float  b    = (float)(-(r32d * r32d));
    float  z1c  = (float)(r32d * c32d);
    float  z1s  = (float)(r32d * s32d);

    double r512 = exp(-512.0 * sd * Kd);
    double Th512 = 512.0 * (double)theta;
    float  Z16c = (float)(r512 * cos(Th512));
    float  Z16s = (float)(r512 * sin(Th512));

    g_P0[m] = make_float4(theta, sigma, coef, a);
    g_P1[m] = make_float4(b, z1c, z1s, Z16c);
    g_P2[m] = Z16s;
}

// ---------------------------------------------------------------------------
// k1: modal bank, TWO modes per iteration (independent recurrence chains
// interleave -> 2x ILP in the 8-cycle dependence window, half the loop
// overhead). Carrier-W init + exact mid-tile rotation, as round 4.
// ---------------------------------------------------------------------------
__global__ void __launch_bounds__(32 * WPB) k1_bank(int T) {
    int gtid   = blockIdx.x * blockDim.x + threadIdx.x;
    int warp_t = gtid >> 5;
    int lane   = threadIdx.x & 31;
    int base   = warp_t * SPAN + lane;
    if (base >= T) return;
    int c = blockIdx.y;

    float acc[TW];
#pragma unroll
    for (int j = 0; j < TW; ++j) acc[j] = 0.0f;

    float tp0 = (float)(base + 1);
    float nk0 = __fmul_rn((float)base, KF);

    int m0 = c * CHUNK;

    // prefetch pair 0
    float4 nA0 = g_P0[m0],     nA1 = g_P0[m0 + 1];
    float4 nB0 = g_P1[m0],     nB1 = g_P1[m0 + 1];
    float  nC0 = g_P2[m0],     nC1 = g_P2[m0 + 1];

    for (int q = 0; q < CHUNK; q += 2) {
        float4 A0 = nA0, A1 = nA1, B0 = nB0, B1 = nB1;
        float  C0 = nC0, C1 = nC1;
        if (q + 2 < CHUNK) {
            int mq = m0 + q + 2;
            nA0 = g_P0[mq];     nA1 = g_P0[mq + 1];
            nB0 = g_P1[mq];     nB1 = g_P1[mq + 1];
            nC0 = g_P2[mq];     nC1 = g_P2[mq + 1];
        }

        // ---- init both modes: one accurate sincos + envelope each ----
        float s0e, c0e, s0o, c0o;
        sincos_acc(__fmul_rn(tp0, A0.x), s0e, c0e);
        sincos_acc(__fmul_rn(tp0, A1.x), s0o, c0o);
        float Ee = __fmul_rn(A0.z, __expf(-__fmul_rn(A0.y, nk0)));
        float Eo = __fmul_rn(A1.z, __expf(-__fmul_rn(A1.y, nk0)));
        float Wime = __fmul_rn(Ee, s0e), Wree = __fmul_rn(Ee, c0e);
        float Wimo = __fmul_rn(Eo, s0o), Wreo = __fmul_rn(Eo, c0o);

        float ae = A0.w, be = B0.x, z1ce = B0.y, z1se = B0.z;
        float ao = A1.w, bo = B1.x, z1co = B1.y, z1so = B1.z;

        float v0e = Wime;
        float v1e = __fmaf_rn(Wree, z1se, __fmul_rn(Wime, z1ce));
        float v0o = Wimo;
        float v1o = __fmaf_rn(Wreo, z1so, __fmul_rn(Wimo, z1co));
        acc[0] = __fadd_rn(acc[0], __fadd_rn(v0e, v0o));
        acc[1] = __fadd_rn(acc[1], __fadd_rn(v1e, v1o));
#pragma unroll
        for (int j = 2; j < 16; ++j) {
            float v2e = __fmaf_rn(ae, v1e, __fmul_rn(be, v0e));
            float v2o = __fmaf_rn(ao, v1o, __fmul_rn(bo, v0o));
            acc[j] = __fadd_rn(acc[j], __fadd_rn(v2e, v2o));
            v0e = v1e; v1e = v2e;
            v0o = v1o; v1o = v2o;
        }

        // ---- exact resync at j=16: W <- W * Z16 (both modes) ----
        float Z16ce = B0.w, Z16se = C0;
        float Z16co = B1.w, Z16so = C1;
        float Wre2e = __fmaf_rn(Wree, Z16ce, -__fmul_rn(Wime, Z16se));
        float Wim2e = __fmaf_rn(Wime, Z16ce,  __fmul_rn(Wree, Z16se));
        float Wre2o = __fmaf_rn(Wreo, Z16co, -__fmul_rn(Wimo, Z16so));
        float Wim2o = __fmaf_rn(Wimo, Z16co,  __fmul_rn(Wreo, Z16so));
        v0e = Wim2e;
        v1e = __fmaf_rn(Wre2e, z1se, __fmul_rn(Wim2e, z1ce));
        v0o = Wim2o;
        v1o = __fmaf_rn(Wre2o, z1so, __fmul_rn(Wim2o, z1co));
        acc[16] = __fadd_rn(acc[16], __fadd_rn(v0e, v0o));
        acc[17] = __fadd_rn(acc[17], __fadd_rn(v1e, v1o));
#pragma unroll
        for (int j = 18; j < TW; ++j) {
            float v2e = __fmaf_rn(ae, v1e, __fmul_rn(be, v0e));
            float v2o = __fmaf_rn(ao, v1o, __fmul_rn(bo, v0o));
            acc[j] = __fadd_rn(acc[j], __fadd_rn(v2e, v2o));
            v0e = v1e; v1e = v2e;
            v0o = v1o; v1o = v2o;
        }
    }

#pragma unroll
    for (int j = 0; j < TW; ++j) {
        int t = base + 32 * j;
        if (t < T) g_part[c][t] = acc[j];
    }
}

// ---------------------------------------------------------------------------
// k2: fused diff + max + normalize with software grid barrier.
// Grid (87 blocks) < 148 SMs -> all blocks co-resident -> barrier is safe.
// ---------------------------------------------------------------------------
__global__ void k2_fused(int T, float* __restrict__ out) {
    __shared__ float sm[257];
    int t = blockIdx.x * blockDim.x + threadIdx.x;

    float s = 0.0f;
    if (t < T) {
#pragma unroll 8
        for (int c = 0; c < NCHUNK; ++c) s += g_part[c][t];
    }
    sm[threadIdx.x + 1] = s;
    if (threadIdx.x == 0) {
        float p = 0.0f;
        int tp = (int)(blockIdx.x * blockDim.x) - 1;
        if (tp >= 0 && tp < T) {
            for (int c = 0; c < NCHUNK; ++c) p += g_part[c][tp];
        }
        sm[0] = p;
    }
    __syncthreads();

    float ir = 0.0f;
    if (t < T) {
        float prev = (t == 0) ? 0.0f : sm[threadIdx.x];
        ir = __fdiv_rn(__fsub_rn(s, prev), KF);
        atomicMax(&g_maxbits, __float_as_uint(fabsf(ir)));
    }

    // ---- grid barrier ----
    __threadfence();
    __syncthreads();
    if (threadIdx.x == 0) {
        atomicAdd(&g_bar, 1u);
        while (atomicOr(&g_bar, 0u) < gridDim.x) { }
    }
    __syncthreads();
    __threadfence();

    if (t < T) {
        float mx = __uint_as_float(atomicOr(&g_maxbits, 0u));
        out[t] = __fdiv_rn(ir, __fadd_rn(mx, 1e-8f));
    }
}

// ---------------------------------------------------------------------------
extern "C" void kernel_launch(void* const* d_in, const int* in_sizes, int n_in,
                              void* d_out, int out_size) {
    (void)in_sizes; (void)n_in;
    const float* mu   = (const float*)d_in[0];
    const float* Dr   = (const float*)d_in[1];
    const float* T0r  = (const float*)d_in[2];
    const float* Lyr  = (const float*)d_in[3];
    const float* xor_ = (const float*)d_in[4];
    const float* yor_ = (const float*)d_in[5];

    int T = out_size;
    if (T > MAX_T) T = MAX_T;

    k0_setup<<<NMODES / 32, 32>>>(mu, Dr, T0r, Lyr, xor_, yor_);

    int warps_t  = (T + SPAN - 1) / SPAN;
    int blocks_x = (warps_t + WPB - 1) / WPB;
    dim3 g1(blocks_x, NCHUNK);
    k1_bank<<<g1, 32 * WPB>>>(T);

    int gb = (T + 255) / 256;
    k2_fused<<<gb, 256>>>(T, (float*)d_out);
}

// round 7
// speedup vs baseline: 1.3022x; 1.3022x over previous
#include <cuda_runtime.h>
#include <math.h>

#define NMODES   6400
#define MDIM     80
#define NCHUNK   128
#define CHUNK    (NMODES / NCHUNK)      /* 50 modes per chunk */
#define MAX_T    24576
#define TW       32                      /* samples per thread, stride 32 */
#define SPAN     1024                    /* samples per warp tile */
#define WPB      4                       /* warps per block in k1 */

#define KF   ((float)(1.0 / 44100.0))
#define K2F  ((float)((1.0/44100.0)*(1.0/44100.0)))

// per-mode tables
__device__ float4   g_P0[NMODES];   // {theta, sigma, C, a}
__device__ float4   g_P1[NMODES];   // {b, z1c, z1s, Z16c}
__device__ float    g_P2[NMODES];   // {Z16s}
__device__ float    g_part[NCHUNK][MAX_T];
__device__ float    g_ir[MAX_T];
__device__ unsigned g_maxbits;

// ---------------------------------------------------------------------------
// Accurate flag-proof float sine / sincos / cosine. Cody-Waite reduction with
// low-bit-count pi parts (products exact for the n ranges used here).
// ---------------------------------------------------------------------------
__device__ __forceinline__ float sin_acc(float x) {
    const float INV_PI = 0.318309886183790671538f;
    float nf = rintf(__fmul_rn(x, INV_PI));
    int   ni = (int)nf;
    float r = __fmaf_rn(-nf, 3.140625f, x);
    r = __fmaf_rn(-nf, 9.670257568359375e-4f, r);
    r = __fmaf_rn(-nf, 6.2771141529083252e-7f, r);
    float r2 = __fmul_rn(r, r);
    float p  = __fmaf_rn(2.60831598097865935e-06f, r2, -1.98106907191686332e-4f);
    p = __fmaf_rn(p, r2,  8.33307858556509018e-3f);
    p = __fmaf_rn(p, r2, -0.166666597127914429f);
    float s = __fmaf_rn(__fmul_rn(r, r2), p, r);
    return __int_as_float(__float_as_int(s) ^ ((ni & 1) << 31));
}

__device__ __forceinline__ void sincos_acc(float x, float& so, float& co) {
    const float INV_PI = 0.318309886183790671538f;
    float nf = rintf(__fmul_rn(x, INV_PI));
    int   sgn = ((int)nf & 1) << 31;
    float r = __fmaf_rn(-nf, 3.140625f, x);
    r = __fmaf_rn(-nf, 9.670257568359375e-4f, r);
    r = __fmaf_rn(-nf, 6.2771141529083252e-7f, r);
    float r2 = __fmul_rn(r, r);
    float ps = __fmaf_rn(2.60831598097865935e-06f, r2, -1.98106907191686332e-4f);
    ps = __fmaf_rn(ps, r2,  8.33307858556509018e-3f);
    ps = __fmaf_rn(ps, r2, -0.166666597127914429f);
    float s = __fmaf_rn(__fmul_rn(r, r2), ps, r);
    float pc = __fmaf_rn(2.44331571e-5f, r2, -1.38873162e-3f);
    pc = __fmaf_rn(pc, r2, 4.16666456e-2f);
    pc = __fmaf_rn(pc, r2, -0.5f);
    float c = __fmaf_rn(pc, r2, 1.0f);
    so = __int_as_float(__float_as_int(s) ^ sgn);
    co = __int_as_float(__float_as_int(c) ^ sgn);
}

// cos(x) = (-1)^(n+1) sin(r),  x = (n+1/2)pi + r.  (n+1/2) exact in float;
// products with 8/9-bit pi parts exact for n <= ~127. Valid |x| < ~400.
__device__ __forceinline__ float cos_accf(float x) {
    const float INV_PI = 0.318309886183790671538f;
    float nf = rintf(__fmaf_rn(x, INV_PI, -0.5f));
    int   ni = (int)nf;
    float nh = __fadd_rn(nf, 0.5f);                 // exact
    float r = __fmaf_rn(-nh, 3.140625f, x);
    r = __fmaf_rn(-nh, 9.670257568359375e-4f, r);
    r = __fmaf_rn(-nh, 6.2771141529083252e-7f, r);
    r = __fmaf_rn(-nh, 1.2154201256553420e-10f, r);
    float r2 = __fmul_rn(r, r);
    float p  = __fmaf_rn(2.60831598097865935e-06f, r2, -1.98106907191686332e-4f);
    p = __fmaf_rn(p, r2,  8.33307858556509018e-3f);
    p = __fmaf_rn(p, r2, -0.166666597127914429f);
    float s = __fmaf_rn(__fmul_rn(r, r2), p, r);
    return __int_as_float(__float_as_int(s) ^ ((~ni & 1) << 31));
}

__device__ __forceinline__ double softplus_d(double x) {
    return (x > 0.0) ? x + log1p(exp(-x)) : log1p(exp(x));
}
__device__ __forceinline__ float sigmoid_f(float x) {
    // amplitude-only; __expf handles +-large args (inf/0) correctly
    return __fdiv_rn(1.0f, __fadd_rn(1.0f, __expf(-x)));
}

// ---------------------------------------------------------------------------
// k0: per-mode setup, FP64 minimized. Scalar input transforms computed ONCE
// per block by 6 parallel threads (one double transcendental each) ->
// shared broadcast. Per mode only sincos(32*theta) + exp(-32*sigma*K) remain
// in double (phase-critical recurrence coefficients); Z16 = z1^16 via 4
// complex squarings in double DFMA. All amplitude-only math in float.
// ---------------------------------------------------------------------------
__global__ void __launch_bounds__(128) k0_setup(
                         const float* __restrict__ mu_raw,
                         const float* __restrict__ D_raw,
                         const float* __restrict__ T0_raw,
                         const float* __restrict__ Ly_raw,
                         const float* __restrict__ xo_raw,
                         const float* __restrict__ yo_raw) {
    __shared__ float sc[6];   // mu, Dm, T0m, Ly, xo, hy
    int tid = threadIdx.x;
    if (tid == 0) sc[0] = __fadd_rn((float)softplus_d((double)*mu_raw),  1e-4f);
    if (tid == 1) sc[1] = __fadd_rn((float)softplus_d((double)*D_raw),   1e-4f);
    if (tid == 2) sc[2] = __fadd_rn((float)softplus_d((double)*T0_raw),  1e-4f);
    if (tid == 3) {
        float hLy = __fmul_rn(__fadd_rn((float)tanh((double)*Ly_raw), 1.0f), 0.5f);
        sc[3] = __fadd_rn(1.1f, __fmul_rn(2.9f, hLy));
    }
    if (tid == 4) {
        float hx = __fmul_rn(__fadd_rn((float)tanh((double)*xo_raw), 1.0f), 0.5f);
        sc[4] = __fadd_rn(0.49f, __fmul_rn(0.51f, hx));
    }
    if (tid == 5) sc[5] = __fmul_rn(__fadd_rn((float)tanh((double)*yo_raw), 1.0f), 0.5f);
    __syncthreads();

    int m = blockIdx.x * blockDim.x + tid;
    if (m == 0) g_maxbits = 0u;
    if (m >= NMODES) return;

    float mu = sc[0], Dm = sc[1], T0m = sc[2], Ly = sc[3], xo = sc[4], hy = sc[5];
    float yo = __fadd_rn(__fmul_rn(0.51f, Ly), __fmul_rn(__fmul_rn(0.49f, Ly), hy));
    float yi = __fmul_rn(0.467f, Ly);

    int mi = m / MDIM + 1;
    int nj = m % MDIM + 1;
    const float PIf = (float)M_PI;

    // ---- phase-critical: g1 -> omega -> theta, explicit f32 RN chain ----
    float mf = (float)mi, nf = (float)nj;
    float t1 = __fmul_rn(mf, PIf);
    float t2 = __fdiv_rn(__fmul_rn(nf, PIf), Ly);
    float g1 = __fadd_rn(__fmul_rn(t1, t1), __fmul_rn(t2, t2));
    float om_sq = __fadd_rn(__fmul_rn(T0m, g1),
                            __fmul_rn(__fmul_rn(Dm, g1), g1));
    float omega = __fsqrt_rn(fmaxf(om_sq, 0.0f));
    float theta = __fmul_rn(omega, KF);

    const double OM2d   = 2.0 * M_PI * 500.0;
    const double DOMSQd = OM2d * OM2d;
    const double ALPHAd = 3.0 * log(10.0) / DOMSQd * (DOMSQd / 6.0);
    const double BETAd  = 3.0 * log(10.0) / DOMSQd * (1.0 / 2.0 - 1.0 / 6.0);
    float om2f  = __fmul_rn(omega, omega);
    float sigma = __fadd_rn((float)ALPHAd, __fmul_rn((float)BETAd, om2f));

    // ---- amplitude-only path: all float ----
    const float MAXOMf = (float)(10000.0 * 2.0 * M_PI);
    const float LOWOMf = (float)(20.0 * 2.0 * M_PI);
    float a1 = __fdiv_rn(__fsub_rn(MAXOMf, omega), 100.0f);
    float a2 = __fdiv_rn(__fsub_rn(omega, LOWOMf), 100.0f);
    float valid = __fmul_rn(sigmoid_f(a1), sigmoid_f(a2));

    const float XIPI = (float)(0.335 * M_PI);
    float inw = __fmul_rn(cos_accf(__fmul_rn(XIPI, mf)),
                          cos_accf(__fdiv_rn(__fmul_rn(__fmul_rn(yi, PIf), nf), Ly)));
    float outw = __fmul_rn(cos_accf(__fmul_rn(__fmul_rn(xo, PIf), mf)),
                           cos_accf(__fdiv_rn(__fmul_rn(__fmul_rn(yo, PIf), nf), Ly)));

    float ms = __fmul_rn(__fmul_rn(0.25f, mu), Ly);
    float E  = __expf(-__fmul_rn(sigma, KF));
    float P  = __fmul_rn(outw, inw);
    P = __fmul_rn(P, K2F);
    P = __fmul_rn(P, E);
    P = __fdiv_rn(P, ms);
    P = __fmul_rn(P, valid);

    float coef = __fdiv_rn(P, __fadd_rn(sin_acc(theta), 1e-8f));

    // ---- phase-critical recurrence coeffs: 3 double transcendentals ----
    double sd   = (double)sigma;
    double Kd   = 1.0 / 44100.0;
    double Th32 = 32.0 * (double)theta;         // exact
    double c32d, s32d;
    sincos(Th32, &s32d, &c32d);
    double r32d = exp(-32.0 * sd * Kd);
    float  a    = (float)(2.0 * r32d * c32d);
    float  b    = (float)(-(r32d * r32d));
    float  z1c  = (float)(r32d * c32d);
    float  z1s  = (float)(r32d * s32d);

    // Z16 = (r32 * e^{i*32theta})^16 via 4 complex squarings (double DFMA)
    double zr = r32d * c32d, zi = r32d * s32d;
#pragma unroll
    for (int k = 0; k < 4; ++k) {
        double nzr = zr * zr - zi * zi;
        double nzi = 2.0 * zr * zi;
        zr = nzr; zi = nzi;
    }
    float Z16c = (float)zr;
    float Z16s = (float)zi;

    g_P0[m] = make_float4(theta, sigma, coef, a);
    g_P1[m] = make_float4(b, z1c, z1s, Z16c);
    g_P2[m] = Z16s;
}

// ---------------------------------------------------------------------------
// k1: modal bank (round-4 form). Thread owns samples {base + 32j : j<32}.
// One accurate sincos builds carrier W; j=16 resync = exact rotation W*Z16.
// ---------------------------------------------------------------------------
__global__ void __launch_bounds__(32 * WPB) k1_bank(int T) {
    int gtid   = blockIdx.x * blockDim.x + threadIdx.x;
    int warp_t = gtid >> 5;
    int lane   = threadIdx.x & 31;
    int base   = warp_t * SPAN + lane;
    if (base >= T) return;
    int c = blockIdx.y;

    float acc[TW];
#pragma unroll
    for (int j = 0; j < TW; ++j) acc[j] = 0.0f;

    float tp0 = (float)(base + 1);
    float nk0 = __fmul_rn((float)base, KF);

    int m0 = c * CHUNK;

    // prefetch mode 0
    float4 nP0 = g_P0[m0];
    float4 nP1 = g_P1[m0];
    float  nP2 = g_P2[m0];

    for (int q = 0; q < CHUNK; ++q) {
        float4 p0 = nP0; float4 p1 = nP1; float p2 = nP2;
        if (q + 1 < CHUNK) {
            nP0 = g_P0[m0 + q + 1];
            nP1 = g_P1[m0 + q + 1];
            nP2 = g_P2[m0 + q + 1];
        }
        float th = p0.x, sg = p0.y, C = p0.z, a = p0.w;
        float b = p1.x, z1c = p1.y, z1s = p1.z, Z16c = p1.w, Z16s = p2;

        // ---- init: one accurate sincos + envelope ----
        float s0, c0;
        sincos_acc(__fmul_rn(tp0, th), s0, c0);
        float E   = __fmul_rn(C, __expf(-__fmul_rn(sg, nk0)));
        float Wim = __fmul_rn(E, s0);
        float Wre = __fmul_rn(E, c0);

        float v0 = Wim;
        float v1 = __fmaf_rn(Wre, z1s, __fmul_rn(Wim, z1c));
        acc[0] = __fadd_rn(acc[0], v0);
        acc[1] = __fadd_rn(acc[1], v1);
#pragma unroll
        for (int j = 2; j < 16; ++j) {
            float v2 = __fmaf_rn(a, v1, __fmul_rn(b, v0));
            acc[j] = __fadd_rn(acc[j], v2);
            v0 = v1; v1 = v2;
        }

        // ---- exact resync at j=16: W <- W * Z16 ----
        float Wre2 = __fmaf_rn(Wre, Z16c, -__fmul_rn(Wim, Z16s));
        float Wim2 = __fmaf_rn(Wim, Z16c,  __fmul_rn(Wre, Z16s));
        v0 = Wim2;
        v1 = __fmaf_rn(Wre2, z1s, __fmul_rn(Wim2, z1c));
        acc[16] = __fadd_rn(acc[16], v0);
        acc[17] = __fadd_rn(acc[17], v1);
#pragma unroll
        for (int j = 18; j < TW; ++j) {
            float v2 = __fmaf_rn(a, v1, __fmul_rn(b, v0));
            acc[j] = __fadd_rn(acc[j], v2);
            v0 = v1; v1 = v2;
        }
    }

#pragma unroll
    for (int j = 0; j < TW; ++j) {
        int t = base + 32 * j;
        if (t < T) g_part[c][t] = acc[j];
    }
}

// ---------------------------------------------------------------------------
// k2: sum chunks, first difference / K, track max|ir|
// ---------------------------------------------------------------------------
__global__ void k2_diff(int T) {
    __shared__ float sm[257];
    int t = blockIdx.x * blockDim.x + threadIdx.x;

    float s = 0.0f;
    if (t < T) {
#pragma unroll 8
        for (int c = 0; c < NCHUNK; ++c) s += g_part[c][t];
    }
    sm[threadIdx.x + 1] = s;
    if (threadIdx.x == 0) {
        float p = 0.0f;
        int tp = (int)(blockIdx.x * blockDim.x) - 1;
        if (tp >= 0 && tp < T) {
            for (int c = 0; c < NCHUNK; ++c) p += g_part[c][tp];
        }
        sm[0] = p;
    }
    __syncthreads();
    if (t >= T) return;

    float prev = (t == 0) ? 0.0f : sm[threadIdx.x];
    float ir = __fdiv_rn(__fsub_rn(s, prev), KF);
    g_ir[t] = ir;
    atomicMax(&g_maxbits, __float_as_uint(fabsf(ir)));
}

// ---------------------------------------------------------------------------
// k3: peak normalize
// ---------------------------------------------------------------------------
__global__ void k3_norm(int T, float* __restrict__ out) {
    int t = blockIdx.x * blockDim.x + threadIdx.x;
    if (t >= T) return;
    float mx = __uint_as_float(g_maxbits);
    out[t] = __fdiv_rn(g_ir[t], __fadd_rn(mx, 1e-8f));
}

// ---------------------------------------------------------------------------
extern "C" void kernel_launch(void* const* d_in, const int* in_sizes, int n_in,
                              void* d_out, int out_size) {
    (void)in_sizes; (void)n_in;
    const float* mu   = (const float*)d_in[0];
    const float* Dr   = (const float*)d_in[1];
    const float* T0r  = (const float*)d_in[2];
    const float* Lyr  = (const float*)d_in[3];
    const float* xor_ = (const float*)d_in[4];
    const float* yor_ = (const float*)d_in[5];

    int T = out_size;
    if (T > MAX_T) T = MAX_T;

    k0_setup<<<NMODES / 128, 128>>>(mu, Dr, T0r, Lyr, xor_, yor_);

    int warps_t  = (T + SPAN - 1) / SPAN;
    int blocks_x = (warps_t + WPB - 1) / WPB;
    dim3 g1(blocks_x, NCHUNK);
    k1_bank<<<g1, 32 * WPB>>>(T);

    int gb = (T + 255) / 256;
    k2_diff<<<gb, 256>>>(T);
    k3_norm<<<gb, 256>>>(T, (float*)d_out);
}